// round 17
// baseline (speedup 1.0000x reference)
#include <cuda_runtime.h>
#include <cuda_bf16.h>
#include <cuda_fp16.h>
#include <math.h>
#include <stdint.h>

// Problem constants
#define BATCH 4096
#define DIN   1024
#define DH    2048
#define DOUT  1024
#define NEXP  16

// Tiling: CTA 128x128, BK=64, 16 warps (4x4) of 32x32 tiles, pure fp16
#define BM 128
#define BN 128
#define BK 64
#define NSTAGE 3
#define NTHREADS 512
#define ROWH 72                           // 64 data halfs + 8 pad (144B rows)
#define TILEB (128 * ROWH * 2)            // 18432 B per matrix tile
#define AH_OFF 0
#define BH_OFF TILEB
#define STAGEB (2 * TILEB)                // 36864
#define DYNSMEM (NSTAGE * STAGEB)         // 110592 (2 CTAs/SM)

#define NPERSIST 304                      // 2 x 152 SMs (work-stealing: safe if fewer)

// exp_w conversion chunking (ticket work-stealing inside gemm<0>)
#define CVT_N4     (NEXP * DH * DH / 4)   // 16M float4
#define CVT_CHUNK  32768                  // float4 per chunk
#define CVT_NCHUNK (CVT_N4 / CVT_CHUNK)   // 512

// Scratch (device globals — no allocation allowed)
__device__ __half g_obs_h[BATCH * DIN];
__device__ __half g_prew_h[DH * DIN];
__device__ __half g_expw_h[NEXP * DH * DH];
__device__ __half g_postw_h[DOUT * DH];
__device__ __half g_x1_h[BATCH * DH];
__device__ __half g_x2_h[BATCH * DH];
__device__ int   g_rows[BATCH];
__device__ int   g_pos [BATCH];
__device__ int   g_cnt[NEXP];
__device__ int   g_off[NEXP];
__device__ int   g_tk[4];                 // tile tickets s1/s2/s3 + cvt ticket

// ---------------------------------------------------------------------------
__device__ __forceinline__ uint32_t smem_u32(const void* p) {
    uint32_t a;
    asm("{ .reg .u64 t; cvta.to.shared.u64 t, %1; cvt.u32.u64 %0, t; }"
        : "=r"(a) : "l"(p));
    return a;
}

__device__ __forceinline__ void cp_async16(uint32_t smem, const void* g) {
    asm volatile("cp.async.cg.shared.global [%0], [%1], 16;" :: "r"(smem), "l"(g) : "memory");
}
__device__ __forceinline__ void cp_commit() {
    asm volatile("cp.async.commit_group;" ::: "memory");
}
__device__ __forceinline__ void cp_wait1() {
    asm volatile("cp.async.wait_group 1;" ::: "memory");
}

__device__ __forceinline__ void ldsm4(uint32_t* r, uint32_t addr) {
    asm volatile("ldmatrix.sync.aligned.m8n8.x4.shared.b16 {%0,%1,%2,%3}, [%4];"
        : "=r"(r[0]), "=r"(r[1]), "=r"(r[2]), "=r"(r[3]) : "r"(addr));
}

__device__ __forceinline__ void mma_f16(float* c, const uint32_t* a, const uint32_t* b) {
    asm volatile(
        "mma.sync.aligned.m16n8k16.row.col.f32.f16.f16.f32 "
        "{%0,%1,%2,%3}, {%4,%5,%6,%7}, {%8,%9}, {%0,%1,%2,%3};"
        : "+f"(c[0]), "+f"(c[1]), "+f"(c[2]), "+f"(c[3])
        : "r"(a[0]), "r"(a[1]), "r"(a[2]), "r"(a[3]), "r"(b[0]), "r"(b[1]));
}

__device__ __forceinline__ void cvt_one(const float4* s, uint2* d) {
    float4 v = *s;
    __half2 h0 = __floats2half2_rn(v.x, v.y);
    __half2 h1 = __floats2half2_rn(v.z, v.w);
    *d = make_uint2(*(uint32_t*)&h0, *(uint32_t*)&h1);
}

// ---------------------------------------------------------------------------
// Block 0: group rows by expert + reset tickets.
// Blocks 1..: convert the three small fp32 buffers to fp16.
// ---------------------------------------------------------------------------
__global__ void group_conv_kernel(const int* __restrict__ idx,
                                  const float* __restrict__ s0, __half* __restrict__ d0, int n0,
                                  const float* __restrict__ s1, __half* __restrict__ d1, int n1,
                                  const float* __restrict__ s2, __half* __restrict__ d2, int n2)
{
    if (blockIdx.x == 0) {
        __shared__ int s_cnt[NEXP];
        __shared__ int s_off[NEXP];
        __shared__ int s_fill[NEXP];
        int t = threadIdx.x;
        if (t < 4) g_tk[t] = 0;
        if (t < NEXP) s_cnt[t] = 0;
        __syncthreads();
        for (int b = t; b < BATCH; b += blockDim.x)
            atomicAdd(&s_cnt[idx[b]], 1);
        __syncthreads();
        if (t == 0) {
            int acc = 0;
            for (int e = 0; e < NEXP; e++) {
                s_off[e]  = acc;
                acc      += s_cnt[e];
                s_fill[e] = 0;
            }
        }
        __syncthreads();
        for (int b = t; b < BATCH; b += blockDim.x) {
            int e = idx[b];
            int p = s_off[e] + atomicAdd(&s_fill[e], 1);
            g_rows[p] = b;
            g_pos[b]  = p;
        }
        if (t < NEXP) { g_cnt[t] = s_cnt[t]; g_off[t] = s_off[t]; }
    } else {
        int total = n0 + n1 + n2;
        int base  = (blockIdx.x - 1) * blockDim.x + threadIdx.x;
        int stride = (gridDim.x - 1) * blockDim.x;
        for (int i = base; i < total; i += stride) {
            const float* s; __half* d; int j = i;
            if      (j < n0)          { s = s0; d = d0; }
            else if ((j -= n0) < n1)  { s = s1; d = d1; }
            else    { j -= n1;          s = s2; d = d2; }
            cvt_one((const float4*)s + j, (uint2*)d + j);
        }
    }
}

// ---------------------------------------------------------------------------
// Persistent pure-fp16 tensor-core GEMM, fused bias + tanh:
//   C = tanh(A_h @ B_h^T + bias)    (fp32 accumulate)
// Fixed grid of CTAs pulls (m,n,e) tile tickets from g_tk[MODE].
// MODE 0: C row = g_pos[m] (fp16 out) + post-loop ticket conversion of exp_w.
// MODE 1: grouped experts (fp16 out). MODE 2: C row = g_rows[m] (fp32 out).
// TM/TN/TE: ticket-space tile counts (m fastest -> same-B tiles adjacent).
// ---------------------------------------------------------------------------
template<int MODE, int TM, int TN, int TE>
__global__ void __launch_bounds__(NTHREADS, 2)
gemm_mma(const __half* __restrict__ Ah,
         const __half* __restrict__ Bwh,
         const float* __restrict__ bias,
         __half* __restrict__ Ch, float* __restrict__ Cf,
         int N, int K,
         const float* __restrict__ cvt_src, __half* __restrict__ cvt_dst)
{
    extern __shared__ char smc[];
    const uint32_t smu = smem_u32(smc);

    const int tid  = threadIdx.x;
    const int lane = tid & 31;
    const int warp = tid >> 5;
    const int wm   = (warp & 3) * 32;   // 4 warps along M
    const int wn   = (warp >> 2) * 32;  // 4 warps along N

    // ---- lane-invariant offsets (hoisted out of the tile loop) ----
    const int q  = lane >> 3;
    const int s8 = lane & 7;
    uint32_t aoff[2], boff[2];
#pragma unroll
    for (int mf = 0; mf < 2; mf++) {
        int row = wm + mf * 16 + (q & 1) * 8 + s8;
        int col = (q >> 1) * 8;
        aoff[mf] = (uint32_t)(row * ROWH + col) * 2;
    }
#pragma unroll
    for (int p = 0; p < 2; p++) {
        int row = wn + p * 16 + (q >> 1) * 8 + s8;
        int col = (q & 1) * 8;
        boff[p] = (uint32_t)(row * ROWH + col) * 2;
    }
    // cp.async lane coordinates (row/col within tile)
    const int cprA = tid >> 3, cpcA = tid & 7;          // chunk l: row += l*64
    const uint32_t soff0 = (uint32_t)cprA * (ROWH * 2) + (uint32_t)cpcA * 16;
    const uint32_t soff1 = soff0 + 64 * (ROWH * 2);

    __shared__ int s_tk;

    for (;;) {
        __syncthreads();
        if (tid == 0) s_tk = atomicAdd(&g_tk[MODE], 1);
        __syncthreads();
        const int t = s_tk;
        if (t >= TM * TN * TE) break;

        const int mt = t % TM;
        const int nt = (t / TM) % TN;
        const int e  = t / (TM * TN);

        const int Mv = (MODE == 1) ? g_cnt[e] : BATCH;
        const int m0 = mt * BM;
        if (m0 >= Mv) continue;
        const int n0    = nt * BN;
        const int abase = (MODE == 1) ? g_off[e] + m0 : m0;
        const __half* Bh = (MODE == 1) ? Bwh + (size_t)e * DH * DH : Bwh;
        const float*  bp = (MODE == 1) ? bias + (size_t)e * DH : bias;

        // ---- per-tile global pointers ----
        int ar0 = abase + cprA;
        int ar1 = abase + cprA + 64;
        if (MODE == 1) {
            ar0 = (ar0 < BATCH) ? ar0 : (BATCH - 1);
            ar1 = (ar1 < BATCH) ? ar1 : (BATCH - 1);
        }
        const __half* gah0 = Ah + (size_t)ar0 * K + cpcA * 8;
        const __half* gah1 = Ah + (size_t)ar1 * K + cpcA * 8;
        const __half* gbh0 = Bh + (size_t)(n0 + cprA) * K + cpcA * 8;
        const __half* gbh1 = Bh + (size_t)(n0 + cprA + 64) * K + cpcA * 8;

        const int KT = K / BK;

        // ---- prologue: stages 0 and 1 ----
#pragma unroll
        for (int s = 0; s < 2; s++) {
            const uint32_t sb = smu + s * STAGEB;
            const int ko = s * BK;
            cp_async16(sb + AH_OFF + soff0, gah0 + ko);
            cp_async16(sb + AH_OFF + soff1, gah1 + ko);
            cp_async16(sb + BH_OFF + soff0, gbh0 + ko);
            cp_async16(sb + BH_OFF + soff1, gbh1 + ko);
            cp_commit();
        }

        float acc[2][4][4];
#pragma unroll
        for (int i = 0; i < 2; i++)
#pragma unroll
            for (int j = 0; j < 4; j++)
#pragma unroll
                for (int rr = 0; rr < 4; rr++) acc[i][j][rr] = 0.0f;

        int sbuf = 0;
        for (int kt = 0; kt < KT; kt++) {
            cp_wait1();
            __syncthreads();

            if (kt + 2 < KT) {
                int snext = sbuf + 2; if (snext >= NSTAGE) snext -= NSTAGE;
                const uint32_t sb = smu + snext * STAGEB;
                const int ko = (kt + 2) * BK;
                cp_async16(sb + AH_OFF + soff0, gah0 + ko);
                cp_async16(sb + AH_OFF + soff1, gah1 + ko);
                cp_async16(sb + BH_OFF + soff0, gbh0 + ko);
                cp_async16(sb + BH_OFF + soff1, gbh1 + ko);
            }
            cp_commit();

            const uint32_t base = smu + sbuf * STAGEB;
#pragma unroll
            for (int ks = 0; ks < BK / 16; ks++) {
                const uint32_t kb2 = (uint32_t)ks * 32;
                uint32_t ah[2][4], bhv[2][4];
#pragma unroll
                for (int mf = 0; mf < 2; mf++)
                    ldsm4(ah[mf], base + AH_OFF + aoff[mf] + kb2);
#pragma unroll
                for (int p = 0; p < 2; p++)
                    ldsm4(bhv[p], base + BH_OFF + boff[p] + kb2);
#pragma unroll
                for (int mf = 0; mf < 2; mf++)
#pragma unroll
                    for (int nf = 0; nf < 4; nf++)
                        mma_f16(acc[mf][nf], ah[mf], &bhv[nf >> 1][(nf & 1) * 2]);
            }
            __syncthreads();
            if (++sbuf == NSTAGE) sbuf = 0;
        }

        // ---- epilogue: bias + tanh + store ----
        const int lr = lane >> 2;
        const int lc = lane & 3;
#pragma unroll
        for (int mf = 0; mf < 2; mf++) {
#pragma unroll
            for (int half = 0; half < 2; half++) {
                const int gm = m0 + wm + mf * 16 + lr + half * 8;
                if (gm >= Mv) continue;
                int crow;
                if      (MODE == 0) crow = g_pos[gm];
                else if (MODE == 1) crow = (abase - m0) + gm;
                else                crow = g_rows[gm];
                const size_t cb = (size_t)crow * N + n0 + wn + 2 * lc;
#pragma unroll
                for (int nf = 0; nf < 4; nf++) {
                    const int cc = n0 + wn + nf * 8 + 2 * lc;
                    float vx = tanhf(acc[mf][nf][half * 2 + 0] + bp[cc]);
                    float vy = tanhf(acc[mf][nf][half * 2 + 1] + bp[cc + 1]);
                    if (MODE == 2) {
                        *(float2*)(Cf + cb + nf * 8) = make_float2(vx, vy);
                    } else {
                        *(__half2*)(Ch + cb + nf * 8) = __floats2half2_rn(vx, vy);
                    }
                }
            }
        }
    }

    // ---- MODE 0 only: work-stealing conversion of exp_w (fp32 -> fp16) ----
    if (MODE == 0) {
        for (;;) {
            __syncthreads();
            if (tid == 0) s_tk = atomicAdd(&g_tk[3], 1);
            __syncthreads();
            const int t = s_tk;
            if (t >= CVT_NCHUNK) break;
            const float4* src = (const float4*)cvt_src + (size_t)t * CVT_CHUNK + tid;
            uint2*        dst = (uint2*)cvt_dst        + (size_t)t * CVT_CHUNK + tid;
#pragma unroll 4
            for (int i = 0; i < CVT_CHUNK; i += NTHREADS)
                cvt_one(src + i, dst + i);
        }
    }
}

// ---------------------------------------------------------------------------
extern "C" void kernel_launch(void* const* d_in, const int* in_sizes, int n_in,
                              void* d_out, int out_size)
{
    const float* obs    = (const float*)d_in[0];
    const int*   sw     = (const int*)  d_in[1];
    const float* pre_w  = (const float*)d_in[2];
    const float* pre_b  = (const float*)d_in[3];
    const float* exp_w  = (const float*)d_in[4];
    const float* exp_b  = (const float*)d_in[5];
    const float* post_w = (const float*)d_in[6];
    const float* post_b = (const float*)d_in[7];
    float*       out    = (float*)d_out;

    __half *obs_h, *prew_h, *expw_h, *postw_h, *x1_h, *x2_h;
    cudaGetSymbolAddress((void**)&obs_h,  g_obs_h);
    cudaGetSymbolAddress((void**)&prew_h, g_prew_h);
    cudaGetSymbolAddress((void**)&expw_h, g_expw_h);
    cudaGetSymbolAddress((void**)&postw_h, g_postw_h);
    cudaGetSymbolAddress((void**)&x1_h, g_x1_h);
    cudaGetSymbolAddress((void**)&x2_h, g_x2_h);

    cudaFuncSetAttribute((const void*)gemm_mma<0, BATCH/BM, DH/BN, 1>,
                         cudaFuncAttributeMaxDynamicSharedMemorySize, DYNSMEM);
    cudaFuncSetAttribute((const void*)gemm_mma<1, BATCH/BM, DH/BN, NEXP>,
                         cudaFuncAttributeMaxDynamicSharedMemorySize, DYNSMEM);
    cudaFuncSetAttribute((const void*)gemm_mma<2, BATCH/BM, DOUT/BN, 1>,
                         cudaFuncAttributeMaxDynamicSharedMemorySize, DYNSMEM);

    // Grouping + small conversions (obs, pre_w, post_w) + ticket reset
    group_conv_kernel<<<297, 256>>>(
        sw,
        obs,    obs_h,   BATCH * DIN / 4,
        pre_w,  prew_h,  DH * DIN / 4,
        post_w, postw_h, DOUT * DH / 4);

    // Stage 1 (persistent): x1[g_pos[b]] = tanh(obs[b] @ pre_w^T + pre_b)
    // + overlapped exp_w conversion via ticket loop
    gemm_mma<0, BATCH/BM, DH/BN, 1><<<NPERSIST, NTHREADS, DYNSMEM>>>(
        obs_h, prew_h, pre_b, x1_h, nullptr, DH, DIN, exp_w, expw_h);

    // Stage 2 (persistent): grouped expert GEMM (fp16 out)
    gemm_mma<1, BATCH/BM, DH/BN, NEXP><<<NPERSIST, NTHREADS, DYNSMEM>>>(
        x1_h, expw_h, exp_b, x2_h, nullptr, DH, DH, nullptr, nullptr);

    // Stage 3 (persistent): out[g_rows[p]] = tanh(x2[p] @ post_w^T + post_b)
    gemm_mma<2, BATCH/BM, DOUT/BN, 1><<<NPERSIST, NTHREADS, DYNSMEM>>>(
        x2_h, postw_h, post_b, nullptr, out, DOUT, DH, nullptr, nullptr);
}